// round 2
// baseline (speedup 1.0000x reference)
#include <cuda_runtime.h>
#include <cuda_bf16.h>
#include <math.h>

#define L 4
#define C 256
#define H 128
#define W 256
#define HW (H*W)
#define CD 128
#define KP 256
#define KTOT 2304          // C*9
#define KSPLIT 6
#define KCH (KTOT/KSPLIT)  // 384

// ---------------- scratch (static device globals; no allocation) ----------------
__device__ float g_scores[L*HW];
__device__ float g_mask[L*HW];
__device__ float g_supp[L*HW];
__device__ float g_ss[L*HW];
__device__ int   g_topidx[L*KP];
__device__ float g_part[L*KSPLIT*CD*KP];
__device__ float g_qkv[L*CD*KP];
__device__ float g_desc2[L*CD*KP];
__device__ float g_proj[L*CD*KP];
__device__ float g_s[L*CD*KP];
__device__ float g_sortd[L*CD*KP];
__device__ float g_final[L*3*KP];
__device__ float g_theta[L*6];

// =================================================================
// 1) convS: 3x3 conv 256->1 + sigmoid over full maps
//    grid (W/16, H/16, L), 256 threads
// =================================================================
__global__ void __launch_bounds__(256)
convS_kernel(const float* __restrict__ feats,
             const float* __restrict__ w,
             const float* __restrict__ b) {
    const int l  = blockIdx.z;
    const int x0 = blockIdx.x * 16, y0 = blockIdx.y * 16;
    const int tx = threadIdx.x & 15, ty = threadIdx.x >> 4;
    __shared__ float sin_[8][18][18];
    __shared__ float sw[8][9];
    float acc = 0.f;
    for (int c0 = 0; c0 < C; c0 += 8) {
        __syncthreads();
        for (int idx = threadIdx.x; idx < 8*324; idx += 256) {
            int cc = idx / 324, r = idx - cc*324;
            int yy = r / 18, xx = r - yy*18;
            int gy = y0 + yy - 1, gx = x0 + xx - 1;
            float v = 0.f;
            if (gy >= 0 && gy < H && gx >= 0 && gx < W)
                v = feats[((l*C + c0+cc)*H + gy)*W + gx];
            sin_[cc][yy][xx] = v;
        }
        for (int idx = threadIdx.x; idx < 72; idx += 256)
            sw[idx/9][idx%9] = w[(c0 + idx/9)*9 + (idx%9)];
        __syncthreads();
        #pragma unroll
        for (int cc = 0; cc < 8; cc++) {
            float s = 0.f;
            #pragma unroll
            for (int ky = 0; ky < 3; ky++)
                #pragma unroll
                for (int kx = 0; kx < 3; kx++)
                    s += sin_[cc][ty+ky][tx+kx] * sw[cc][ky*3+kx];
            acc += s;
        }
    }
    float z = acc + b[0];
    g_scores[l*HW + (y0+ty)*W + (x0+tx)] = 1.f / (1.f + expf(-z));
}

// =================================================================
// 2) NMS: 9x9 maxpool (radius 4), literal 2-iteration simple_nms
//    grid (W/32, H/32, L), 1024 threads
// =================================================================
__device__ __forceinline__ float mp9(const float* __restrict__ src, int l,
                                     float sm[40][40], float rm[40][32]) {
    const int x0 = blockIdx.x * 32, y0 = blockIdx.y * 32;
    const int tid = threadIdx.x;
    for (int idx = tid; idx < 1600; idx += 1024) {
        int yy = idx / 40, xx = idx - yy*40;
        int gy = y0 + yy - 4, gx = x0 + xx - 4;
        sm[yy][xx] = (gy >= 0 && gy < H && gx >= 0 && gx < W)
                     ? src[l*HW + gy*W + gx] : -INFINITY;
    }
    __syncthreads();
    for (int idx = tid; idx < 1280; idx += 1024) {
        int yy = idx >> 5, xx = idx & 31;
        float m = -INFINITY;
        #pragma unroll
        for (int dx = 0; dx < 9; dx++) m = fmaxf(m, sm[yy][xx+dx]);
        rm[yy][xx] = m;
    }
    __syncthreads();
    const int tx = tid & 31, ty = tid >> 5;
    float m = -INFINITY;
    #pragma unroll
    for (int dy = 0; dy < 9; dy++) m = fmaxf(m, rm[ty+dy][tx]);
    return m;
}

__global__ void __launch_bounds__(1024) nms1_kernel() {
    __shared__ float sm[40][40]; __shared__ float rm[40][32];
    int l = blockIdx.z;
    float mx = mp9(g_scores, l, sm, rm);
    int pix = l*HW + (blockIdx.y*32 + (threadIdx.x>>5))*W + blockIdx.x*32 + (threadIdx.x&31);
    g_mask[pix] = (g_scores[pix] == mx) ? 1.f : 0.f;
}
__global__ void __launch_bounds__(1024) nms2_kernel() {
    __shared__ float sm[40][40]; __shared__ float rm[40][32];
    int l = blockIdx.z;
    float mx = mp9(g_mask, l, sm, rm);
    int pix = l*HW + (blockIdx.y*32 + (threadIdx.x>>5))*W + blockIdx.x*32 + (threadIdx.x&31);
    float supp = (mx > 0.f) ? 1.f : 0.f;
    g_supp[pix] = supp;
    g_ss[pix] = (supp > 0.f) ? 0.f : g_scores[pix];
}
__global__ void __launch_bounds__(1024) nms3_kernel() {
    __shared__ float sm[40][40]; __shared__ float rm[40][32];
    int l = blockIdx.z;
    float mx = mp9(g_ss, l, sm, rm);
    int pix = l*HW + (blockIdx.y*32 + (threadIdx.x>>5))*W + blockIdx.x*32 + (threadIdx.x&31);
    float nm = (g_ss[pix] == mx) ? 1.f : 0.f;
    float old = g_mask[pix], supp = g_supp[pix];
    g_mask[pix] = (old != 0.f || (nm != 0.f && supp == 0.f)) ? 1.f : 0.f;
}

// =================================================================
// 3) top-k 256 with exact jax tie semantics. grid(L), 1024 threads
// =================================================================
__global__ void __launch_bounds__(1024) topk_kernel() {
    const int l = blockIdx.x;
    __shared__ unsigned long long keys[4096];
    __shared__ int cnt;
    if (threadIdx.x == 0) cnt = 0;
    for (int i = threadIdx.x; i < 4096; i += 1024) keys[i] = 0xFFFFFFFFFFFFFFFFull;
    __syncthreads();
    for (int i = threadIdx.x; i < HW; i += 1024) {
        float m = g_mask[l*HW + i];
        float v = (m != 0.f) ? g_scores[l*HW + i] : 0.f;
        if (v > 0.f) {
            int p = atomicAdd(&cnt, 1);
            if (p < 4096)
                keys[p] = (((unsigned long long)(~__float_as_uint(v))) << 32) | (unsigned)i;
        }
    }
    __syncthreads();
    // bitonic ascending (smaller key = higher score, then lower index)
    for (int k = 2; k <= 4096; k <<= 1)
        for (int j = k >> 1; j > 0; j >>= 1) {
            for (int i = threadIdx.x; i < 4096; i += 1024) {
                int ixj = i ^ j;
                if (ixj > i) {
                    bool up = ((i & k) == 0);
                    unsigned long long a = keys[i], bb = keys[ixj];
                    if ((a > bb) == up) { keys[i] = bb; keys[ixj] = a; }
                }
            }
            __syncthreads();
        }
    int cc = cnt; if (cc > 4096) cc = 4096;
    if (threadIdx.x < KP && threadIdx.x < cc)
        g_topidx[l*KP + threadIdx.x] = (int)(keys[threadIdx.x] & 0xFFFFFFFFull);
    __syncthreads();
    if (threadIdx.x == 0 && cc < KP) {   // fill with zero-score positions, ascending idx
        int fill = cc;
        for (int i = 0; i < HW && fill < KP; i++) {
            float m = g_mask[l*HW + i];
            float v = (m != 0.f) ? g_scores[l*HW + i] : 0.f;
            if (v == 0.f) g_topidx[l*KP + fill++] = i;
        }
    }
}

// =================================================================
// 4) convD only at keypoints: implicit GEMM 128x32 per block, split-K
//    grid (8 kp-tiles, KSPLIT, L), 256 threads
// =================================================================
__global__ void __launch_bounds__(256)
descgemm_kernel(const float* __restrict__ feats,
                const float* __restrict__ wD) {
    const int l = blockIdx.z, ks = blockIdx.y, kt = blockIdx.x;
    const int tx = threadIdx.x & 31, ty = threadIdx.x >> 5;
    __shared__ float Wt[128][33];
    __shared__ float Pt[32][33];
    __shared__ int kpy[32], kpx[32];
    if (threadIdx.x < 32) {
        int idx = g_topidx[l*KP + kt*32 + threadIdx.x];
        kpy[threadIdx.x] = idx >> 8;   // /W
        kpx[threadIdx.x] = idx & 255;  // %W
    }
    float acc[16];
    #pragma unroll
    for (int r = 0; r < 16; r++) acc[r] = 0.f;
    const int kkbase = ks * KCH;
    for (int t = 0; t < KCH/32; t++) {
        int kk0 = kkbase + t*32;
        __syncthreads();
        for (int i = threadIdx.x; i < 4096; i += 256) {
            int c = i >> 5, q = i & 31;
            Wt[c][q] = wD[c*KTOT + kk0 + q];
        }
        for (int i = threadIdx.x; i < 1024; i += 256) {
            int kkl = i >> 5, kc = i & 31;
            int kk = kk0 + kkl;
            int ci = kk / 9, rem = kk - ci*9;
            int dy = rem/3 - 1, dx = rem - (rem/3)*3 - 1;
            int y = kpy[kc] + dy, x = kpx[kc] + dx;
            float v = 0.f;
            if (y >= 0 && y < H && x >= 0 && x < W)
                v = feats[((l*C + ci)*H + y)*W + x];
            Pt[kkl][kc] = v;
        }
        __syncthreads();
        #pragma unroll 8
        for (int kkl = 0; kkl < 32; kkl++) {
            float p = Pt[kkl][tx];
            #pragma unroll
            for (int r = 0; r < 16; r++)
                acc[r] += Wt[ty*16 + r][kkl] * p;
        }
    }
    #pragma unroll
    for (int r = 0; r < 16; r++)
        g_part[(((l*KSPLIT + ks)*CD + ty*16 + r)*KP) + kt*32 + tx] = acc[r];
}

// 4b) reduce split-K + bias + relu + L2-normalize per (l,k). grid(KP,L), 128 thr
__global__ void __launch_bounds__(128)
descnorm_kernel(const float* __restrict__ bD) {
    const int k = blockIdx.x, l = blockIdx.y, c = threadIdx.x;
    float v = bD[c];
    #pragma unroll
    for (int ks = 0; ks < KSPLIT; ks++)
        v += g_part[(((l*KSPLIT + ks)*CD + c)*KP) + k];
    v = fmaxf(v, 0.f);
    __shared__ float red[4];
    float sq = v*v;
    #pragma unroll
    for (int o = 16; o > 0; o >>= 1) sq += __shfl_xor_sync(0xffffffffu, sq, o);
    if ((c & 31) == 0) red[c >> 5] = sq;
    __syncthreads();
    float nrm = sqrtf(red[0] + red[1] + red[2] + red[3]);
    g_qkv[(l*CD + c)*KP + k] = v / fmaxf(nrm, 1e-12f);
}

// =================================================================
// 5) per-keypoint 4x4 cross-layer attention + residual. grid(KP), 128 thr
// =================================================================
__global__ void __launch_bounds__(128) attn_kernel() {
    const int k = blockIdx.x, c = threadIdx.x;
    __shared__ float qs[L][CD];
    __shared__ float attn[L][L];
    __shared__ float prob[L][L];
    for (int l = 0; l < L; l++) qs[l][c] = g_qkv[(l*CD + c)*KP + k];
    __syncthreads();
    if (c < 16) {
        int n = c >> 2, m = c & 3;
        float d = 0.f;
        for (int i = 0; i < CD; i++) d += qs[n][i] * qs[m][i];
        attn[n][m] = d / sqrtf((float)CD);
    }
    __syncthreads();
    if (c < 4) {
        float mx = attn[c][0];
        for (int m = 1; m < 4; m++) mx = fmaxf(mx, attn[c][m]);
        float e[4], s = 0.f;
        for (int m = 0; m < 4; m++) { e[m] = expf(attn[c][m] - mx); s += e[m]; }
        for (int m = 0; m < 4; m++) prob[c][m] = e[m] / s;
    }
    __syncthreads();
    for (int l = 0; l < L; l++) {
        float msg = prob[l][0]*qs[0][c] + prob[l][1]*qs[1][c]
                  + prob[l][2]*qs[2][c] + prob[l][3]*qs[3][c];
        g_desc2[(l*CD + c)*KP + k] = 2.f*qs[l][c] + msg;
    }
}

// =================================================================
// 6) proj: conv1d 3-tap 128->128 + relu. grid(8, L), 256 threads
// =================================================================
__global__ void __launch_bounds__(256)
proj_kernel(const float* __restrict__ w, const float* __restrict__ b) {
    const int l = blockIdx.y, kt = blockIdx.x;
    const int tx = threadIdx.x & 31, ty = threadIdx.x >> 5;
    const int k0 = kt * 32;
    __shared__ float Dt[128][34];
    __shared__ float ws[16][384];
    for (int i = threadIdx.x; i < 128*34; i += 256) {
        int ci = i / 34, col = i - ci*34;
        int kk = k0 + col - 1;
        Dt[ci][col] = (kk >= 0 && kk < KP) ? g_desc2[(l*CD + ci)*KP + kk] : 0.f;
    }
    float acc[16];
    #pragma unroll
    for (int r = 0; r < 16; r++) acc[r] = 0.f;
    for (int ic = 0; ic < 128; ic += 16) {
        __syncthreads();
        for (int i = threadIdx.x; i < 16*384; i += 256) {
            int il = i / 384, rest = i - il*384;
            int o = rest / 3, d = rest - o*3;
            ws[il][rest] = w[o*384 + (ic + il)*3 + d];
        }
        __syncthreads();
        #pragma unroll 4
        for (int il = 0; il < 16; il++) {
            float pm = Dt[ic+il][tx], p0 = Dt[ic+il][tx+1], pp = Dt[ic+il][tx+2];
            #pragma unroll
            for (int r = 0; r < 16; r++) {
                int o = ty*16 + r;
                acc[r] += ws[il][o*3]*pm + ws[il][o*3+1]*p0 + ws[il][o*3+2]*pp;
            }
        }
    }
    #pragma unroll
    for (int r = 0; r < 16; r++) {
        int o = ty*16 + r;
        g_proj[(l*CD + o)*KP + k0 + tx] = fmaxf(acc[r] + b[o], 0.f);
    }
}

// 7) projS: 1x1 conv 128->128 (no relu). grid(8, L), 256 threads
__global__ void __launch_bounds__(256)
projs_kernel(const float* __restrict__ w, const float* __restrict__ b) {
    const int l = blockIdx.y, kt = blockIdx.x;
    const int tx = threadIdx.x & 31, ty = threadIdx.x >> 5;
    const int k0 = kt * 32;
    __shared__ float Pt[128][33];
    __shared__ float ws[32][128];
    for (int i = threadIdx.x; i < 4096; i += 256) {
        int ci = i >> 5, col = i & 31;
        Pt[ci][col] = g_proj[(l*CD + ci)*KP + k0 + col];
    }
    float acc[16];
    #pragma unroll
    for (int r = 0; r < 16; r++) acc[r] = 0.f;
    for (int ic = 0; ic < 128; ic += 32) {
        __syncthreads();
        for (int i = threadIdx.x; i < 4096; i += 256) {
            int il = i & 31, o = i >> 5;
            ws[il][o] = w[o*128 + ic + il];
        }
        __syncthreads();
        #pragma unroll 8
        for (int il = 0; il < 32; il++) {
            float p = Pt[ic+il][tx];
            #pragma unroll
            for (int r = 0; r < 16; r++)
                acc[r] += ws[il][ty*16 + r] * p;
        }
    }
    #pragma unroll
    for (int r = 0; r < 16; r++) {
        int o = ty*16 + r;
        g_s[(l*CD + o)*KP + k0 + tx] = acc[r] + b[o];
    }
}

// =================================================================
// 8) per-(l,cd) row: stable argsort(-s), gather proj. grid(512), 256 thr
// =================================================================
__device__ __forceinline__ unsigned fkey(float f) {
    unsigned u = __float_as_uint(f);
    return (u & 0x80000000u) ? ~u : (u | 0x80000000u);
}
__global__ void __launch_bounds__(256) sortrow_kernel() {
    const int row = blockIdx.x;
    const int j = threadIdx.x;
    __shared__ unsigned long long sk[KP];
    float sv = g_s[row*KP + j];
    unsigned fk = fkey(sv) ^ 0xFFFFFFFFu;  // descending s
    sk[j] = (((unsigned long long)fk) << 32) | (unsigned)j;
    __syncthreads();
    for (int k2 = 2; k2 <= KP; k2 <<= 1)
        for (int jj = k2 >> 1; jj > 0; jj >>= 1) {
            int ixj = j ^ jj;
            if (ixj > j) {
                bool up = ((j & k2) == 0);
                unsigned long long a = sk[j], bb = sk[ixj];
                if ((a > bb) == up) { sk[j] = bb; sk[ixj] = a; }
            }
            __syncthreads();
        }
    int src = (int)(sk[j] & 0xFFFFFFFFull);
    g_sortd[row*KP + j] = g_proj[row*KP + src];
}

// 9) final: 1x1 conv 128->3. grid(12), 256 threads
__global__ void __launch_bounds__(256)
final_kernel(const float* __restrict__ w, const float* __restrict__ b) {
    const int lo = blockIdx.x;
    const int l = lo / 3, o = lo - l*3;
    const int j = threadIdx.x;
    float acc = b[o];
    for (int cd = 0; cd < CD; cd++)
        acc += w[o*CD + cd] * g_sortd[(l*CD + cd)*KP + j];
    g_final[lo*KP + j] = acc;
}

// 10) theta: subtract layer0, argmin|.| (first occurrence), build affine. 1 block
__global__ void __launch_bounds__(384) theta_kernel() {
    const int tid = threadIdx.x;
    const int wrp = tid >> 5, lane = tid & 31;
    __shared__ float md[L][3];
    if (wrp < 12) {
        int l = wrp / 3, o = wrp - l*3;
        unsigned long long best = 0xFFFFFFFFFFFFFFFFull;
        for (int j = lane; j < KP; j += 32) {
            float d = g_final[(l*3 + o)*KP + j] - g_final[o*KP + j];
            float a = fabsf(d);
            unsigned long long key = (((unsigned long long)__float_as_uint(a)) << 32) | (unsigned)j;
            best = (key < best) ? key : best;
        }
        #pragma unroll
        for (int s = 16; s > 0; s >>= 1) {
            unsigned long long oth = __shfl_xor_sync(0xffffffffu, best, s);
            best = (oth < best) ? oth : best;
        }
        if (lane == 0) md[l][o] = __uint_as_float((unsigned)(best >> 32));
    }
    __syncthreads();
    if (tid < L) {
        float th = md[tid][2], tx = md[tid][0], ty = md[tid][1];
        float cc = cosf(th), ss = sinf(th);
        g_theta[tid*6 + 0] = cc;  g_theta[tid*6 + 1] = -ss; g_theta[tid*6 + 2] = tx;
        g_theta[tid*6 + 3] = ss;  g_theta[tid*6 + 4] = cc;  g_theta[tid*6 + 5] = ty;
    }
}

// =================================================================
// 11) affine grid + bilinear sample. grid(H, L), 256 threads (j)
// =================================================================
__global__ void __launch_bounds__(256)
sample_kernel(const float* __restrict__ feats, float* __restrict__ out) {
    const int l = blockIdx.y, i = blockIdx.x, j = threadIdx.x;
    float t0 = g_theta[l*6+0], t1 = g_theta[l*6+1], t2 = g_theta[l*6+2];
    float t3 = g_theta[l*6+3], t4 = g_theta[l*6+4], t5 = g_theta[l*6+5];
    float X = (j + 0.5f) * (2.0f / W) - 1.0f;
    float Y = (i + 0.5f) * (2.0f / H) - 1.0f;
    float gx = t0*X + t1*Y + t2;
    float gy = t3*X + t4*Y + t5;
    float ix = ((gx + 1.0f) * W - 1.0f) * 0.5f;
    float iy = ((gy + 1.0f) * H - 1.0f) * 0.5f;
    float x0f = floorf(ix), y0f = floorf(iy);
    float x1f = x0f + 1.0f, y1f = y0f + 1.0f;
    float wa = (x1f - ix) * (y1f - iy);
    float wb = (ix - x0f) * (y1f - iy);
    float wc = (x1f - ix) * (iy - y0f);
    float wd = (ix - x0f) * (iy - y0f);
    bool vx0 = (x0f >= 0.f) && (x0f <= (float)(W-1));
    bool vx1 = (x1f >= 0.f) && (x1f <= (float)(W-1));
    bool vy0 = (y0f >= 0.f) && (y0f <= (float)(H-1));
    bool vy1 = (y1f >= 0.f) && (y1f <= (float)(H-1));
    int x0 = (int)fminf(fmaxf(x0f, 0.f), (float)(W-1));
    int x1 = (int)fminf(fmaxf(x1f, 0.f), (float)(W-1));
    int y0 = (int)fminf(fmaxf(y0f, 0.f), (float)(H-1));
    int y1 = (int)fminf(fmaxf(y1f, 0.f), (float)(H-1));
    bool va = vx0 && vy0, vb = vx1 && vy0, vc = vx0 && vy1, vd = vx1 && vy1;
    #pragma unroll 4
    for (int c = 0; c < C; c++) {
        const float* base = feats + (size_t)((l*C + c)*H) * W;
        float A = va ? base[y0*W + x0] : 0.f;
        float B = vb ? base[y0*W + x1] : 0.f;
        float Cv = vc ? base[y1*W + x0] : 0.f;
        float D = vd ? base[y1*W + x1] : 0.f;
        out[(size_t)((l*C + c)*H + i)*W + j] = A*wa + B*wb + Cv*wc + D*wd;
    }
}

// =================================================================
extern "C" void kernel_launch(void* const* d_in, const int* in_sizes, int n_in,
                              void* d_out, int out_size) {
    (void)in_sizes; (void)n_in; (void)out_size;
    const float* feats   = (const float*)d_in[0];
    const float* convS_w = (const float*)d_in[1];
    const float* convS_b = (const float*)d_in[2];
    const float* convD_w = (const float*)d_in[3];
    const float* convD_b = (const float*)d_in[4];
    const float* proj_w  = (const float*)d_in[5];
    const float* proj_b  = (const float*)d_in[6];
    const float* projS_w = (const float*)d_in[7];
    const float* projS_b = (const float*)d_in[8];
    const float* final_w = (const float*)d_in[9];
    const float* final_b = (const float*)d_in[10];
    float* out = (float*)d_out;

    convS_kernel<<<dim3(W/16, H/16, L), 256>>>(feats, convS_w, convS_b);

    dim3 ng(W/32, H/32, L);
    nms1_kernel<<<ng, 1024>>>();
    nms2_kernel<<<ng, 1024>>>();
    nms3_kernel<<<ng, 1024>>>();
    nms2_kernel<<<ng, 1024>>>();
    nms3_kernel<<<ng, 1024>>>();

    topk_kernel<<<L, 1024>>>();

    descgemm_kernel<<<dim3(KP/32, KSPLIT, L), 256>>>(feats, convD_w);
    descnorm_kernel<<<dim3(KP, L), CD>>>(convD_b);
    attn_kernel<<<KP, CD>>>();
    proj_kernel<<<dim3(KP/32, L), 256>>>(proj_w, proj_b);
    projs_kernel<<<dim3(KP/32, L), 256>>>(projS_w, projS_b);
    sortrow_kernel<<<L*CD, KP>>>();
    final_kernel<<<L*3, KP>>>(final_w, final_b);
    theta_kernel<<<1, 384>>>();
    sample_kernel<<<dim3(H, L), 256>>>(feats, out);
}

// round 4
// speedup vs baseline: 1.0646x; 1.0646x over previous
#include <cuda_runtime.h>
#include <cuda_bf16.h>
#include <math.h>

#define L 4
#define C 256
#define H 128
#define W 256
#define HW (H*W)
#define CD 128
#define KP 256
#define KTOT 2304          // C*9
#define KSPLIT 6
#define KCH (KTOT/KSPLIT)  // 384

// ---------------- scratch (static device globals; no allocation) ----------------
__device__ float g_scores[L*HW];
__device__ float g_mask[L*HW];
__device__ float g_mask2[L*HW];
__device__ int   g_topidx[L*KP];
__device__ float g_part[L*KSPLIT*CD*KP];
__device__ float g_desc2[L*CD*KP];
__device__ float g_proj[L*CD*KP];
__device__ float g_s[L*CD*KP];
__device__ float g_sortd[L*CD*KP];
__device__ float g_final[L*3*KP];
__device__ float g_theta[L*6];

// =================================================================
// 1) convS: 3x3 conv 256->1 + sigmoid. 64x16 tile, 4 outputs/thread.
//    grid (W/64, H/16, L), 256 threads
// =================================================================
__global__ void __launch_bounds__(256)
convS_kernel(const float* __restrict__ feats,
             const float* __restrict__ w,
             const float* __restrict__ b) {
    const int l  = blockIdx.z;
    const int x0 = blockIdx.x * 64, y0 = blockIdx.y * 16;
    const int txg = threadIdx.x & 15, ty = threadIdx.x >> 4;
    __shared__ __align__(16) float sin_[8][18][68];   // [cc][yy][xx], xx covers x0-1..x0+64
    __shared__ float sw[8][9];
    float acc[4] = {0.f, 0.f, 0.f, 0.f};
    for (int c0 = 0; c0 < C; c0 += 8) {
        __syncthreads();
        for (int idx = threadIdx.x; idx < 8*18*66; idx += 256) {
            int cc = idx / 1188, r = idx - cc*1188;
            int yy = r / 66, xx = r - yy*66;
            int gy = y0 + yy - 1, gx = x0 + xx - 1;
            float v = 0.f;
            if (gy >= 0 && gy < H && gx >= 0 && gx < W)
                v = feats[((l*C + c0+cc)*H + gy)*W + gx];
            sin_[cc][yy][xx] = v;
        }
        if (threadIdx.x < 72)
            sw[threadIdx.x/9][threadIdx.x%9] = w[(c0 + threadIdx.x/9)*9 + (threadIdx.x%9)];
        __syncthreads();
        #pragma unroll
        for (int cc = 0; cc < 8; cc++) {
            #pragma unroll
            for (int ky = 0; ky < 3; ky++) {
                const float* row = &sin_[cc][ty+ky][txg*4];
                float4 v4 = *reinterpret_cast<const float4*>(row);
                float r4 = row[4], r5 = row[5];
                float w0 = sw[cc][ky*3+0], w1 = sw[cc][ky*3+1], w2 = sw[cc][ky*3+2];
                acc[0] += w0*v4.x + w1*v4.y + w2*v4.z;
                acc[1] += w0*v4.y + w1*v4.z + w2*v4.w;
                acc[2] += w0*v4.z + w1*v4.w + w2*r4;
                acc[3] += w0*v4.w + w1*r4   + w2*r5;
            }
        }
    }
    const float bb = b[0];
    #pragma unroll
    for (int p = 0; p < 4; p++) {
        float z = acc[p] + bb;
        g_scores[l*HW + (y0+ty)*W + x0 + txg*4 + p] = 1.f / (1.f + expf(-z));
    }
}

// =================================================================
// 2a) NMS iter 0: mask = (scores == maxpool9(scores))
//     grid (W/32, H/32, L), 1024 threads
// =================================================================
__global__ void __launch_bounds__(1024) nms1_kernel() {
    __shared__ float sm[40][40];
    __shared__ float rm[40][33];
    const int l = blockIdx.z;
    const int x0 = blockIdx.x * 32, y0 = blockIdx.y * 32;
    const int tid = threadIdx.x;
    for (int idx = tid; idx < 1600; idx += 1024) {
        int yy = idx / 40, xx = idx - yy*40;
        int gy = y0 + yy - 4, gx = x0 + xx - 4;
        sm[yy][xx] = (gy >= 0 && gy < H && gx >= 0 && gx < W)
                     ? g_scores[l*HW + gy*W + gx] : -INFINITY;
    }
    __syncthreads();
    for (int idx = tid; idx < 1280; idx += 1024) {
        int yy = idx >> 5, xx = idx & 31;
        float m = -INFINITY;
        #pragma unroll
        for (int dx = 0; dx < 9; dx++) m = fmaxf(m, sm[yy][xx+dx]);
        rm[yy][xx] = m;
    }
    __syncthreads();
    const int tx = tid & 31, ty = tid >> 5;
    float m = -INFINITY;
    #pragma unroll
    for (int dy = 0; dy < 9; dy++) m = fmaxf(m, rm[ty+dy][tx]);
    int pix = l*HW + (y0+ty)*W + x0 + tx;
    g_mask[pix] = (g_scores[pix] == m) ? 1.f : 0.f;
}

// =================================================================
// 2b) fused NMS iteration: mask_out = mask_in | (new_max & ~supp)
//     supp = mp9(mask_in)>0; ss = supp?0:scores; new_max = ss==mp9(ss)
//     halo 8 on mask_in. grid (W/32, H/32, L), 1024 threads.
//     dir=0: g_mask->g_mask2 ; dir=1: g_mask2->g_mask
// =================================================================
__global__ void __launch_bounds__(1024) nms23_kernel(int dir) {
    const float* __restrict__ min_ = dir ? g_mask2 : g_mask;
    float* __restrict__ mout       = dir ? g_mask  : g_mask2;
    __shared__ float m48[48][48];
    __shared__ float rmA[48][41];
    __shared__ float supp[40][40];
    __shared__ float ss[40][40];
    __shared__ float rmB[40][33];
    const int l = blockIdx.z;
    const int x0 = blockIdx.x * 32, y0 = blockIdx.y * 32;
    const int tid = threadIdx.x;
    // load mask with halo 8
    for (int idx = tid; idx < 2304; idx += 1024) {
        int yy = idx / 48, xx = idx - yy*48;
        int gy = y0 + yy - 8, gx = x0 + xx - 8;
        m48[yy][xx] = (gy >= 0 && gy < H && gx >= 0 && gx < W)
                      ? min_[l*HW + gy*W + gx] : -INFINITY;
    }
    __syncthreads();
    // horizontal max of mask: rmA[48][40] covering x0-4..x0+35
    for (int idx = tid; idx < 1920; idx += 1024) {
        int yy = idx / 40, xx = idx - yy*40;
        float m = -INFINITY;
        #pragma unroll
        for (int dx = 0; dx < 9; dx++) m = fmaxf(m, m48[yy][xx+dx]);
        rmA[yy][xx] = m;
    }
    __syncthreads();
    // vertical max -> supp over tile+halo4; ss = supp?0:scores (OOB = -inf)
    for (int idx = tid; idx < 1600; idx += 1024) {
        int yy = idx / 40, xx = idx - yy*40;
        float m = -INFINITY;
        #pragma unroll
        for (int dy = 0; dy < 9; dy++) m = fmaxf(m, rmA[yy+dy][xx]);
        supp[yy][xx] = m;
        int gy = y0 + yy - 4, gx = x0 + xx - 4;
        float sv = -INFINITY;
        if (gy >= 0 && gy < H && gx >= 0 && gx < W)
            sv = (m > 0.f) ? 0.f : g_scores[l*HW + gy*W + gx];
        ss[yy][xx] = sv;
    }
    __syncthreads();
    // horizontal max of ss
    for (int idx = tid; idx < 1280; idx += 1024) {
        int yy = idx >> 5, xx = idx & 31;
        float m = -INFINITY;
        #pragma unroll
        for (int dx = 0; dx < 9; dx++) m = fmaxf(m, ss[yy][xx+dx]);
        rmB[yy][xx] = m;
    }
    __syncthreads();
    const int tx = tid & 31, ty = tid >> 5;
    float mxB = -INFINITY;
    #pragma unroll
    for (int dy = 0; dy < 9; dy++) mxB = fmaxf(mxB, rmB[ty+dy][tx]);
    float ssc  = ss[ty+4][tx+4];
    float supc = supp[ty+4][tx+4];
    float old  = m48[ty+8][tx+8];
    bool nm = (ssc == mxB);
    bool nmask = (old != 0.f) || (nm && !(supc > 0.f));
    mout[l*HW + (y0+ty)*W + x0 + tx] = nmask ? 1.f : 0.f;
}

// =================================================================
// 3) top-k 256 with exact jax tie semantics. grid(L), 1024 threads.
//    Dual-path bitonic: 1024 keys when cnt<=1024 (common), else 4096.
// =================================================================
__global__ void __launch_bounds__(1024) topk_kernel() {
    const int l = blockIdx.x;
    __shared__ unsigned long long keys[4096];
    __shared__ int cnt;
    if (threadIdx.x == 0) cnt = 0;
    for (int i = threadIdx.x; i < 4096; i += 1024) keys[i] = 0xFFFFFFFFFFFFFFFFull;
    __syncthreads();
    for (int i = threadIdx.x; i < HW; i += 1024) {
        float m = g_mask[l*HW + i];
        float v = (m != 0.f) ? g_scores[l*HW + i] : 0.f;
        if (v > 0.f) {
            int p = atomicAdd(&cnt, 1);
            if (p < 4096)
                keys[p] = (((unsigned long long)(~__float_as_uint(v))) << 32) | (unsigned)i;
        }
    }
    __syncthreads();
    int cc = cnt; if (cc > 4096) cc = 4096;
    if (cc <= 1024) {
        // sort first 1024 slots (all real keys live there); 1 key/thread
        const int i = threadIdx.x;
        for (int k = 2; k <= 1024; k <<= 1)
            for (int j = k >> 1; j > 0; j >>= 1) {
                int ixj = i ^ j;
                if (ixj > i) {
                    bool up = ((i & k) == 0);
                    unsigned long long a = keys[i], bb = keys[ixj];
                    if ((a > bb) == up) { keys[i] = bb; keys[ixj] = a; }
                }
                __syncthreads();
            }
    } else {
        for (int k = 2; k <= 4096; k <<= 1)
            for (int j = k >> 1; j > 0; j >>= 1) {
                for (int i = threadIdx.x; i < 4096; i += 1024) {
                    int ixj = i ^ j;
                    if (ixj > i) {
                        bool up = ((i & k) == 0);
                        unsigned long long a = keys[i], bb = keys[ixj];
                        if ((a > bb) == up) { keys[i] = bb; keys[ixj] = a; }
                    }
                }
                __syncthreads();
            }
    }
    if (threadIdx.x < KP && threadIdx.x < cc)
        g_topidx[l*KP + threadIdx.x] = (int)(keys[threadIdx.x] & 0xFFFFFFFFull);
    __syncthreads();
    if (threadIdx.x == 0 && cc < KP) {   // fill with zero-score positions, ascending idx
        int fill = cc;
        for (int i = 0; i < HW && fill < KP; i++) {
            float m = g_mask[l*HW + i];
            float v = (m != 0.f) ? g_scores[l*HW + i] : 0.f;
            if (v == 0.f) g_topidx[l*KP + fill++] = i;
        }
    }
}

// =================================================================
// 4) convD only at keypoints: implicit GEMM, 4x4 micro-tile, split-K
//    grid (8 kp-tiles, KSPLIT, L), 256 threads
// =================================================================
__global__ void __launch_bounds__(256)
descgemm_kernel(const float* __restrict__ feats,
                const float* __restrict__ wD) {
    const int l = blockIdx.z, ks = blockIdx.y, kt = blockIdx.x;
    const int rowg = threadIdx.x >> 3;   // 0..31 -> rows rowg*4+0..3
    const int colg = threadIdx.x & 7;    // 0..7  -> cols colg*4+0..3
    __shared__ float Wt[128][33];        // [c][kkl]
    __shared__ float Pt[32][36];         // [kkl][kc]
    __shared__ int kpy[32], kpx[32];
    if (threadIdx.x < 32) {
        int idx = g_topidx[l*KP + kt*32 + threadIdx.x];
        kpy[threadIdx.x] = idx >> 8;   // /W
        kpx[threadIdx.x] = idx & 255;  // %W
    }
    float acc[4][4];
    #pragma unroll
    for (int x = 0; x < 4; x++)
        #pragma unroll
        for (int y = 0; y < 4; y++) acc[x][y] = 0.f;
    const int kkbase = ks * KCH;
    for (int t = 0; t < KCH/32; t++) {
        int kk0 = kkbase + t*32;
        __syncthreads();
        for (int i = threadIdx.x; i < 4096; i += 256) {
            int c = i >> 5, q = i & 31;
            Wt[c][q] = wD[c*KTOT + kk0 + q];
        }
        for (int i = threadIdx.x; i < 1024; i += 256) {
            int kkl = i >> 5, kc = i & 31;
            int kk = kk0 + kkl;
            int ci = kk / 9, rem = kk - ci*9;
            int dy = rem/3 - 1, dx = rem - (rem/3)*3 - 1;
            int y = kpy[kc] + dy, x = kpx[kc] + dx;
            float v = 0.f;
            if (y >= 0 && y < H && x >= 0 && x < W)
                v = feats[((l*C + ci)*H + y)*W + x];
            Pt[kkl][kc] = v;
        }
        __syncthreads();
        #pragma unroll 4
        for (int kkl = 0; kkl < 32; kkl++) {
            float wv[4], pv[4];
            #pragma unroll
            for (int x = 0; x < 4; x++) wv[x] = Wt[rowg*4+x][kkl];
            #pragma unroll
            for (int y = 0; y < 4; y++) pv[y] = Pt[kkl][colg*4+y];
            #pragma unroll
            for (int x = 0; x < 4; x++)
                #pragma unroll
                for (int y = 0; y < 4; y++) acc[x][y] += wv[x]*pv[y];
        }
    }
    #pragma unroll
    for (int x = 0; x < 4; x++)
        #pragma unroll
        for (int y = 0; y < 4; y++)
            g_part[(((l*KSPLIT + ks)*CD + rowg*4+x)*KP) + kt*32 + colg*4 + y] = acc[x][y];
}

// =================================================================
// 5) fused: split-K reduce + bias + relu + L2-normalize + 4x4 attention
//    grid(KP), 512 threads (l = tid>>7, c = tid&127)
// =================================================================
__global__ void __launch_bounds__(512)
descnorm_attn_kernel(const float* __restrict__ bD) {
    const int k = blockIdx.x;
    const int tid = threadIdx.x;
    const int l = tid >> 7, c = tid & 127;
    __shared__ float wsum[16];
    __shared__ float qs[L][CD];
    __shared__ float attnm[16];
    __shared__ float prob[16];
    float v = bD[c];
    #pragma unroll
    for (int ks = 0; ks < KSPLIT; ks++)
        v += g_part[(((l*KSPLIT + ks)*CD + c)*KP) + k];
    v = fmaxf(v, 0.f);
    float sq = v*v;
    #pragma unroll
    for (int o = 16; o > 0; o >>= 1) sq += __shfl_xor_sync(0xffffffffu, sq, o);
    if ((tid & 31) == 0) wsum[tid >> 5] = sq;
    __syncthreads();
    float nrm = sqrtf(wsum[l*4] + wsum[l*4+1] + wsum[l*4+2] + wsum[l*4+3]);
    float q = v / fmaxf(nrm, 1e-12f);
    qs[l][c] = q;
    __syncthreads();
    if (tid < 16) {
        int n = tid >> 2, m = tid & 3;
        float d = 0.f;
        for (int i = 0; i < CD; i++) d += qs[n][i] * qs[m][i];
        attnm[tid] = d / sqrtf((float)CD);
    }
    __syncthreads();
    if (tid < 4) {
        float mx = attnm[tid*4];
        for (int m = 1; m < 4; m++) mx = fmaxf(mx, attnm[tid*4+m]);
        float e[4], s = 0.f;
        for (int m = 0; m < 4; m++) { e[m] = expf(attnm[tid*4+m] - mx); s += e[m]; }
        for (int m = 0; m < 4; m++) prob[tid*4+m] = e[m] / s;
    }
    __syncthreads();
    float msg = prob[l*4+0]*qs[0][c] + prob[l*4+1]*qs[1][c]
              + prob[l*4+2]*qs[2][c] + prob[l*4+3]*qs[3][c];
    g_desc2[(l*CD + c)*KP + k] = 2.f*q + msg;
}

// =================================================================
// 6) fused proj (3-tap conv1d + relu) then projS (1x1). grid(8, L), 256 thr
// =================================================================
__global__ void __launch_bounds__(256)
projfused_kernel(const float* __restrict__ w1, const float* __restrict__ b1,
                 const float* __restrict__ w2, const float* __restrict__ b2) {
    const int l = blockIdx.y, kt = blockIdx.x;
    const int tx = threadIdx.x & 31, ty = threadIdx.x >> 5;
    const int k0 = kt * 32;
    __shared__ float Dt[128][34];
    __shared__ float wsbuf[16*384];
    for (int i = threadIdx.x; i < 128*34; i += 256) {
        int ci = i / 34, col = i - ci*34;
        int kk = k0 + col - 1;
        Dt[ci][col] = (kk >= 0 && kk < KP) ? g_desc2[(l*CD + ci)*KP + kk] : 0.f;
    }
    float acc[16];
    #pragma unroll
    for (int r = 0; r < 16; r++) acc[r] = 0.f;
    for (int ic = 0; ic < 128; ic += 16) {
        __syncthreads();
        for (int i = threadIdx.x; i < 16*384; i += 256) {
            int il = i / 384, rest = i - il*384;
            int o = rest / 3, d = rest - o*3;
            wsbuf[il*384 + rest] = w1[o*384 + (ic + il)*3 + d];
        }
        __syncthreads();
        #pragma unroll 4
        for (int il = 0; il < 16; il++) {
            float pm = Dt[ic+il][tx], p0 = Dt[ic+il][tx+1], pp = Dt[ic+il][tx+2];
            #pragma unroll
            for (int r = 0; r < 16; r++) {
                int o = ty*16 + r;
                acc[r] += wsbuf[il*384 + o*3]*pm + wsbuf[il*384 + o*3+1]*p0
                        + wsbuf[il*384 + o*3+2]*pp;
            }
        }
    }
    __syncthreads();   // everyone done reading Dt/wsbuf
    #pragma unroll
    for (int r = 0; r < 16; r++) {
        int o = ty*16 + r;
        float pv = fmaxf(acc[r] + b1[o], 0.f);
        g_proj[(l*CD + o)*KP + k0 + tx] = pv;
        Dt[o][tx] = pv;           // reuse Dt as proj tile [128 out][32 k]
        acc[r] = 0.f;
    }
    // ---- stage B: projS 1x1 ----
    for (int ic = 0; ic < 128; ic += 32) {
        __syncthreads();
        for (int i = threadIdx.x; i < 4096; i += 256) {
            int il = i & 31, o = i >> 5;
            wsbuf[il*128 + o] = w2[o*128 + ic + il];
        }
        __syncthreads();
        #pragma unroll 8
        for (int il = 0; il < 32; il++) {
            float p = Dt[ic+il][tx];
            #pragma unroll
            for (int r = 0; r < 16; r++)
                acc[r] += wsbuf[il*128 + ty*16 + r] * p;
        }
    }
    #pragma unroll
    for (int r = 0; r < 16; r++) {
        int o = ty*16 + r;
        g_s[(l*CD + o)*KP + k0 + tx] = acc[r] + b2[o];
    }
}

// =================================================================
// 7) per-(l,cd) row: stable argsort(-s), gather proj. grid(512), 256 thr
// =================================================================
__device__ __forceinline__ unsigned fkey(float f) {
    unsigned u = __float_as_uint(f);
    return (u & 0x80000000u) ? ~u : (u | 0x80000000u);
}
__global__ void __launch_bounds__(256) sortrow_kernel() {
    const int row = blockIdx.x;
    const int j = threadIdx.x;
    __shared__ unsigned long long sk[KP];
    float sv = g_s[row*KP + j];
    unsigned fk = fkey(sv) ^ 0xFFFFFFFFu;  // descending s
    sk[j] = (((unsigned long long)fk) << 32) | (unsigned)j;
    __syncthreads();
    for (int k2 = 2; k2 <= KP; k2 <<= 1)
        for (int jj = k2 >> 1; jj > 0; jj >>= 1) {
            int ixj = j ^ jj;
            if (ixj > j) {
                bool up = ((j & k2) == 0);
                unsigned long long a = sk[j], bb = sk[ixj];
                if ((a > bb) == up) { sk[j] = bb; sk[ixj] = a; }
            }
            __syncthreads();
        }
    int src = (int)(sk[j] & 0xFFFFFFFFull);
    g_sortd[row*KP + j] = g_proj[row*KP + src];
}

// 8) final: 1x1 conv 128->3. grid(12), 256 threads
__global__ void __launch_bounds__(256)
final_kernel(const float* __restrict__ w, const float* __restrict__ b) {
    const int lo = blockIdx.x;
    const int l = lo / 3, o = lo - l*3;
    const int j = threadIdx.x;
    float acc = b[o];
    for (int cd = 0; cd < CD; cd++)
        acc += w[o*CD + cd] * g_sortd[(l*CD + cd)*KP + j];
    g_final[lo*KP + j] = acc;
}

// 9) theta: subtract layer0, argmin|.| (first occurrence), build affine. 1 block
__global__ void __launch_bounds__(384) theta_kernel() {
    const int tid = threadIdx.x;
    const int wrp = tid >> 5, lane = tid & 31;
    __shared__ float md[L][3];
    if (wrp < 12) {
        int l = wrp / 3, o = wrp - l*3;
        unsigned long long best = 0xFFFFFFFFFFFFFFFFull;
        for (int j = lane; j < KP; j += 32) {
            float d = g_final[(l*3 + o)*KP + j] - g_final[o*KP + j];
            float a = fabsf(d);
            unsigned long long key = (((unsigned long long)__float_as_uint(a)) << 32) | (unsigned)j;
            best = (key < best) ? key : best;
        }
        #pragma unroll
        for (int s = 16; s > 0; s >>= 1) {
            unsigned long long oth = __shfl_xor_sync(0xffffffffu, best, s);
            best = (oth < best) ? oth : best;
        }
        if (lane == 0) md[l][o] = __uint_as_float((unsigned)(best >> 32));
    }
    __syncthreads();
    if (tid < L) {
        float th = md[tid][2], tx = md[tid][0], ty = md[tid][1];
        float cc = cosf(th), ss = sinf(th);
        g_theta[tid*6 + 0] = cc;  g_theta[tid*6 + 1] = -ss; g_theta[tid*6 + 2] = tx;
        g_theta[tid*6 + 3] = ss;  g_theta[tid*6 + 4] = cc;  g_theta[tid*6 + 5] = ty;
    }
}

// =================================================================
// 10) affine grid + bilinear sample, channel-parallel.
//     grid (H, C/8, L), 256 threads (j), 8 channels per thread.
// =================================================================
__global__ void __launch_bounds__(256)
sample_kernel(const float* __restrict__ feats, float* __restrict__ out) {
    const int i = blockIdx.x, c0 = blockIdx.y * 8, l = blockIdx.z;
    const int j = threadIdx.x;
    float t0 = g_theta[l*6+0], t1 = g_theta[l*6+1], t2 = g_theta[l*6+2];
    float t3 = g_theta[l*6+3], t4 = g_theta[l*6+4], t5 = g_theta[l*6+5];
    float X = (j + 0.5f) * (2.0f / W) - 1.0f;
    float Y = (i + 0.5f) * (2.0f / H) - 1.0f;
    float gx = t0*X + t1*Y + t2;
    float gy = t3*X + t4*Y + t5;
    float ix = ((gx + 1.0f) * W - 1.0f) * 0.5f;
    float iy = ((gy + 1.0f) * H - 1.0f) * 0.5f;
    float x0f = floorf(ix), y0f = floorf(iy);
    float x1f = x0f + 1.0f, y1f = y0f + 1.0f;
    float wa = (x1f - ix) * (y1f - iy);
    float wb = (ix - x0f) * (y1f - iy);
    float wc = (x1f - ix) * (iy - y0f);
    float wd = (ix - x0f) * (iy - y0f);
    bool vx0 = (x0f >= 0.f) && (x0f <= (float)(W-1));
    bool vx1 = (x1f >= 0.f) && (x1f <= (float)(W-1));
    bool vy0 = (y0f >= 0.f) && (y0f <= (float)(H-1));
    bool vy1 = (y1f >= 0.f) && (y1f <= (float)(H-1));
    int x0 = (int)fminf(fmaxf(x0f, 0.f), (float)(W-1));
    int x1 = (int)fminf(fmaxf(x1f, 0.f), (float)(W-1));
    int y0 = (int)fminf(fmaxf(y0f, 0.f), (float)(H-1));
    int y1 = (int)fminf(fmaxf(y1f, 0.f), (float)(H-1));
    bool va = vx0 && vy0, vb = vx1 && vy0, vc = vx0 && vy1, vd = vx1 && vy1;
    const int o00 = y0*W + x0, o01 = y0*W + x1, o10 = y1*W + x0, o11 = y1*W + x1;
    #pragma unroll
    for (int cc = 0; cc < 8; cc++) {
        const float* base = feats + (size_t)((l*C + c0 + cc)*H) * W;
        float A  = va ? base[o00] : 0.f;
        float B  = vb ? base[o01] : 0.f;
        float Cv = vc ? base[o10] : 0.f;
        float D  = vd ? base[o11] : 0.f;
        out[(size_t)((l*C + c0 + cc)*H + i)*W + j] = A*wa + B*wb + Cv*wc + D*wd;
    }
}

// =================================================================
extern "C" void kernel_launch(void* const* d_in, const int* in_sizes, int n_in,
                              void* d_out, int out_size) {
    (void)in_sizes; (void)n_in; (void)out_size;
    const float* feats   = (const float*)d_in[0];
    const float* convS_w = (const float*)d_in[1];
    const float* convS_b = (const float*)d_in[2];
    const float* convD_w = (const float*)d_in[3];
    const float* convD_b = (const float*)d_in[4];
    const float* proj_w  = (const float*)d_in[5];
    const float* proj_b  = (const float*)d_in[6];
    const float* projS_w = (const float*)d_in[7];
    const float* projS_b = (const float*)d_in[8];
    const float* final_w = (const float*)d_in[9];
    const float* final_b = (const float*)d_in[10];
    float* out = (float*)d_out;

    convS_kernel<<<dim3(W/64, H/16, L), 256>>>(feats, convS_w, convS_b);

    dim3 ng(W/32, H/32, L);
    nms1_kernel<<<ng, 1024>>>();
    nms23_kernel<<<ng, 1024>>>(0);   // g_mask  -> g_mask2
    nms23_kernel<<<ng, 1024>>>(1);   // g_mask2 -> g_mask

    topk_kernel<<<L, 1024>>>();

    descgemm_kernel<<<dim3(KP/32, KSPLIT, L), 256>>>(feats, convD_w);
    descnorm_attn_kernel<<<KP, 512>>>(convD_b);
    projfused_kernel<<<dim3(KP/32, L), 256>>>(proj_w, proj_b, projS_w, projS_b);
    sortrow_kernel<<<L*CD, KP>>>();
    final_kernel<<<L*3, KP>>>(final_w, final_b);
    theta_kernel<<<1, 384>>>();
    sample_kernel<<<dim3(H, C/8, L), 256>>>(feats, out);
}

// round 5
// speedup vs baseline: 1.0650x; 1.0003x over previous
#include <cuda_runtime.h>
#include <cuda_bf16.h>
#include <math.h>

#define L 4
#define C 256
#define H 128
#define W 256
#define HW (H*W)
#define CD 128
#define KP 256
#define KTOT 2304          // C*9
#define KSPLIT 6
#define KCH (KTOT/KSPLIT)  // 384

// ---------------- scratch (static device globals; no allocation) ----------------
__device__ float g_scores[L*HW];
__device__ float g_mask[L*HW];
__device__ float g_mask2[L*HW];
__device__ int   g_topidx[L*KP];
__device__ float g_part[L*KSPLIT*CD*KP];
__device__ float g_desc2[L*CD*KP];
__device__ float g_proj[L*CD*KP];
__device__ float g_s[L*CD*KP];
__device__ float g_sortd[L*CD*KP];
__device__ float g_final[L*3*KP];
__device__ float g_theta[L*6];

// =================================================================
// 1) convS: 3x3 conv 256->1 + sigmoid. 64x16 tile, 4 outputs/thread.
//    grid (W/64, H/16, L), 256 threads
// =================================================================
__global__ void __launch_bounds__(256)
convS_kernel(const float* __restrict__ feats,
             const float* __restrict__ w,
             const float* __restrict__ b) {
    const int l  = blockIdx.z;
    const int x0 = blockIdx.x * 64, y0 = blockIdx.y * 16;
    const int txg = threadIdx.x & 15, ty = threadIdx.x >> 4;
    __shared__ __align__(16) float sin_[8][18][68];   // [cc][yy][xx], xx covers x0-1..x0+64
    __shared__ float sw[8][9];
    float acc[4] = {0.f, 0.f, 0.f, 0.f};
    for (int c0 = 0; c0 < C; c0 += 8) {
        __syncthreads();
        for (int idx = threadIdx.x; idx < 8*18*66; idx += 256) {
            int cc = idx / 1188, r = idx - cc*1188;
            int yy = r / 66, xx = r - yy*66;
            int gy = y0 + yy - 1, gx = x0 + xx - 1;
            float v = 0.f;
            if (gy >= 0 && gy < H && gx >= 0 && gx < W)
                v = feats[((l*C + c0+cc)*H + gy)*W + gx];
            sin_[cc][yy][xx] = v;
        }
        if (threadIdx.x < 72)
            sw[threadIdx.x/9][threadIdx.x%9] = w[(c0 + threadIdx.x/9)*9 + (threadIdx.x%9)];
        __syncthreads();
        #pragma unroll
        for (int cc = 0; cc < 8; cc++) {
            #pragma unroll
            for (int ky = 0; ky < 3; ky++) {
                const float* row = &sin_[cc][ty+ky][txg*4];
                float4 v4 = *reinterpret_cast<const float4*>(row);
                float r4 = row[4], r5 = row[5];
                float w0 = sw[cc][ky*3+0], w1 = sw[cc][ky*3+1], w2 = sw[cc][ky*3+2];
                acc[0] += w0*v4.x + w1*v4.y + w2*v4.z;
                acc[1] += w0*v4.y + w1*v4.z + w2*v4.w;
                acc[2] += w0*v4.z + w1*v4.w + w2*r4;
                acc[3] += w0*v4.w + w1*r4   + w2*r5;
            }
        }
    }
    const float bb = b[0];
    #pragma unroll
    for (int p = 0; p < 4; p++) {
        float z = acc[p] + bb;
        g_scores[l*HW + (y0+ty)*W + x0 + txg*4 + p] = 1.f / (1.f + expf(-z));
    }
}

// =================================================================
// 2a) NMS iter 0: mask = (scores == maxpool9(scores))
//     grid (W/32, H/32, L), 1024 threads
// =================================================================
__global__ void __launch_bounds__(1024) nms1_kernel() {
    __shared__ float sm[40][40];
    __shared__ float rm[40][33];
    const int l = blockIdx.z;
    const int x0 = blockIdx.x * 32, y0 = blockIdx.y * 32;
    const int tid = threadIdx.x;
    for (int idx = tid; idx < 1600; idx += 1024) {
        int yy = idx / 40, xx = idx - yy*40;
        int gy = y0 + yy - 4, gx = x0 + xx - 4;
        sm[yy][xx] = (gy >= 0 && gy < H && gx >= 0 && gx < W)
                     ? g_scores[l*HW + gy*W + gx] : -INFINITY;
    }
    __syncthreads();
    for (int idx = tid; idx < 1280; idx += 1024) {
        int yy = idx >> 5, xx = idx & 31;
        float m = -INFINITY;
        #pragma unroll
        for (int dx = 0; dx < 9; dx++) m = fmaxf(m, sm[yy][xx+dx]);
        rm[yy][xx] = m;
    }
    __syncthreads();
    const int tx = tid & 31, ty = tid >> 5;
    float m = -INFINITY;
    #pragma unroll
    for (int dy = 0; dy < 9; dy++) m = fmaxf(m, rm[ty+dy][tx]);
    int pix = l*HW + (y0+ty)*W + x0 + tx;
    g_mask[pix] = (g_scores[pix] == m) ? 1.f : 0.f;
}

// =================================================================
// 2b) fused NMS iteration: mask_out = mask_in | (new_max & ~supp)
//     supp = mp9(mask_in)>0; ss = supp?0:scores; new_max = ss==mp9(ss)
//     halo 8 on mask_in. grid (W/32, H/32, L), 1024 threads.
//     dir=0: g_mask->g_mask2 ; dir=1: g_mask2->g_mask
// =================================================================
__global__ void __launch_bounds__(1024) nms23_kernel(int dir) {
    const float* __restrict__ min_ = dir ? g_mask2 : g_mask;
    float* __restrict__ mout       = dir ? g_mask  : g_mask2;
    __shared__ float m48[48][48];
    __shared__ float rmA[48][41];
    __shared__ float supp[40][40];
    __shared__ float ss[40][40];
    __shared__ float rmB[40][33];
    const int l = blockIdx.z;
    const int x0 = blockIdx.x * 32, y0 = blockIdx.y * 32;
    const int tid = threadIdx.x;
    // load mask with halo 8
    for (int idx = tid; idx < 2304; idx += 1024) {
        int yy = idx / 48, xx = idx - yy*48;
        int gy = y0 + yy - 8, gx = x0 + xx - 8;
        m48[yy][xx] = (gy >= 0 && gy < H && gx >= 0 && gx < W)
                      ? min_[l*HW + gy*W + gx] : -INFINITY;
    }
    __syncthreads();
    // horizontal max of mask: rmA[48][40] covering x0-4..x0+35
    for (int idx = tid; idx < 1920; idx += 1024) {
        int yy = idx / 40, xx = idx - yy*40;
        float m = -INFINITY;
        #pragma unroll
        for (int dx = 0; dx < 9; dx++) m = fmaxf(m, m48[yy][xx+dx]);
        rmA[yy][xx] = m;
    }
    __syncthreads();
    // vertical max -> supp over tile+halo4; ss = supp?0:scores (OOB = -inf)
    for (int idx = tid; idx < 1600; idx += 1024) {
        int yy = idx / 40, xx = idx - yy*40;
        float m = -INFINITY;
        #pragma unroll
        for (int dy = 0; dy < 9; dy++) m = fmaxf(m, rmA[yy+dy][xx]);
        supp[yy][xx] = m;
        int gy = y0 + yy - 4, gx = x0 + xx - 4;
        float sv = -INFINITY;
        if (gy >= 0 && gy < H && gx >= 0 && gx < W)
            sv = (m > 0.f) ? 0.f : g_scores[l*HW + gy*W + gx];
        ss[yy][xx] = sv;
    }
    __syncthreads();
    // horizontal max of ss
    for (int idx = tid; idx < 1280; idx += 1024) {
        int yy = idx >> 5, xx = idx & 31;
        float m = -INFINITY;
        #pragma unroll
        for (int dx = 0; dx < 9; dx++) m = fmaxf(m, ss[yy][xx+dx]);
        rmB[yy][xx] = m;
    }
    __syncthreads();
    const int tx = tid & 31, ty = tid >> 5;
    float mxB = -INFINITY;
    #pragma unroll
    for (int dy = 0; dy < 9; dy++) mxB = fmaxf(mxB, rmB[ty+dy][tx]);
    float ssc  = ss[ty+4][tx+4];
    float supc = supp[ty+4][tx+4];
    float old  = m48[ty+8][tx+8];
    bool nm = (ssc == mxB);
    bool nmask = (old != 0.f) || (nm && !(supc > 0.f));
    mout[l*HW + (y0+ty)*W + x0 + tx] = nmask ? 1.f : 0.f;
}

// =================================================================
// 3) top-k 256 with exact jax tie semantics. grid(L), 1024 threads.
//    Dual-path bitonic: 1024 keys when cnt<=1024 (common), else 4096.
// =================================================================
__global__ void __launch_bounds__(1024) topk_kernel() {
    const int l = blockIdx.x;
    __shared__ unsigned long long keys[4096];
    __shared__ int cnt;
    if (threadIdx.x == 0) cnt = 0;
    for (int i = threadIdx.x; i < 4096; i += 1024) keys[i] = 0xFFFFFFFFFFFFFFFFull;
    __syncthreads();
    for (int i = threadIdx.x; i < HW; i += 1024) {
        float m = g_mask[l*HW + i];
        float v = (m != 0.f) ? g_scores[l*HW + i] : 0.f;
        if (v > 0.f) {
            int p = atomicAdd(&cnt, 1);
            if (p < 4096)
                keys[p] = (((unsigned long long)(~__float_as_uint(v))) << 32) | (unsigned)i;
        }
    }
    __syncthreads();
    int cc = cnt; if (cc > 4096) cc = 4096;
    if (cc <= 1024) {
        // sort first 1024 slots (all real keys live there); 1 key/thread
        const int i = threadIdx.x;
        for (int k = 2; k <= 1024; k <<= 1)
            for (int j = k >> 1; j > 0; j >>= 1) {
                int ixj = i ^ j;
                if (ixj > i) {
                    bool up = ((i & k) == 0);
                    unsigned long long a = keys[i], bb = keys[ixj];
                    if ((a > bb) == up) { keys[i] = bb; keys[ixj] = a; }
                }
                __syncthreads();
            }
    } else {
        for (int k = 2; k <= 4096; k <<= 1)
            for (int j = k >> 1; j > 0; j >>= 1) {
                for (int i = threadIdx.x; i < 4096; i += 1024) {
                    int ixj = i ^ j;
                    if (ixj > i) {
                        bool up = ((i & k) == 0);
                        unsigned long long a = keys[i], bb = keys[ixj];
                        if ((a > bb) == up) { keys[i] = bb; keys[ixj] = a; }
                    }
                }
                __syncthreads();
            }
    }
    if (threadIdx.x < KP && threadIdx.x < cc)
        g_topidx[l*KP + threadIdx.x] = (int)(keys[threadIdx.x] & 0xFFFFFFFFull);
    __syncthreads();
    if (threadIdx.x == 0 && cc < KP) {   // fill with zero-score positions, ascending idx
        int fill = cc;
        for (int i = 0; i < HW && fill < KP; i++) {
            float m = g_mask[l*HW + i];
            float v = (m != 0.f) ? g_scores[l*HW + i] : 0.f;
            if (v == 0.f) g_topidx[l*KP + fill++] = i;
        }
    }
}

// =================================================================
// 4) convD only at keypoints: implicit GEMM, 4x4 micro-tile, split-K
//    grid (8 kp-tiles, KSPLIT, L), 256 threads
// =================================================================
__global__ void __launch_bounds__(256)
descgemm_kernel(const float* __restrict__ feats,
                const float* __restrict__ wD) {
    const int l = blockIdx.z, ks = blockIdx.y, kt = blockIdx.x;
    const int rowg = threadIdx.x >> 3;   // 0..31 -> rows rowg*4+0..3
    const int colg = threadIdx.x & 7;    // 0..7  -> cols colg*4+0..3
    __shared__ float Wt[128][33];        // [c][kkl]
    __shared__ float Pt[32][36];         // [kkl][kc]
    __shared__ int kpy[32], kpx[32];
    if (threadIdx.x < 32) {
        int idx = g_topidx[l*KP + kt*32 + threadIdx.x];
        kpy[threadIdx.x] = idx >> 8;   // /W
        kpx[threadIdx.x] = idx & 255;  // %W
    }
    float acc[4][4];
    #pragma unroll
    for (int x = 0; x < 4; x++)
        #pragma unroll
        for (int y = 0; y < 4; y++) acc[x][y] = 0.f;
    const int kkbase = ks * KCH;
    for (int t = 0; t < KCH/32; t++) {
        int kk0 = kkbase + t*32;
        __syncthreads();
        for (int i = threadIdx.x; i < 4096; i += 256) {
            int c = i >> 5, q = i & 31;
            Wt[c][q] = wD[c*KTOT + kk0 + q];
        }
        for (int i = threadIdx.x; i < 1024; i += 256) {
            int kkl = i >> 5, kc = i & 31;
            int kk = kk0 + kkl;
            int ci = kk / 9, rem = kk - ci*9;
            int dy = rem/3 - 1, dx = rem - (rem/3)*3 - 1;
            int y = kpy[kc] + dy, x = kpx[kc] + dx;
            float v = 0.f;
            if (y >= 0 && y < H && x >= 0 && x < W)
                v = feats[((l*C + ci)*H + y)*W + x];
            Pt[kkl][kc] = v;
        }
        __syncthreads();
        #pragma unroll 4
        for (int kkl = 0; kkl < 32; kkl++) {
            float wv[4], pv[4];
            #pragma unroll
            for (int x = 0; x < 4; x++) wv[x] = Wt[rowg*4+x][kkl];
            #pragma unroll
            for (int y = 0; y < 4; y++) pv[y] = Pt[kkl][colg*4+y];
            #pragma unroll
            for (int x = 0; x < 4; x++)
                #pragma unroll
                for (int y = 0; y < 4; y++) acc[x][y] += wv[x]*pv[y];
        }
    }
    #pragma unroll
    for (int x = 0; x < 4; x++)
        #pragma unroll
        for (int y = 0; y < 4; y++)
            g_part[(((l*KSPLIT + ks)*CD + rowg*4+x)*KP) + kt*32 + colg*4 + y] = acc[x][y];
}

// =================================================================
// 5) fused: split-K reduce + bias + relu + L2-normalize + 4x4 attention
//    grid(KP), 512 threads (l = tid>>7, c = tid&127)
// =================================================================
__global__ void __launch_bounds__(512)
descnorm_attn_kernel(const float* __restrict__ bD) {
    const int k = blockIdx.x;
    const int tid = threadIdx.x;
    const int l = tid >> 7, c = tid & 127;
    __shared__ float wsum[16];
    __shared__ float qs[L][CD];
    __shared__ float attnm[16];
    __shared__ float prob[16];
    float v = bD[c];
    #pragma unroll
    for (int ks = 0; ks < KSPLIT; ks++)
        v += g_part[(((l*KSPLIT + ks)*CD + c)*KP) + k];
    v = fmaxf(v, 0.f);
    float sq = v*v;
    #pragma unroll
    for (int o = 16; o > 0; o >>= 1) sq += __shfl_xor_sync(0xffffffffu, sq, o);
    if ((tid & 31) == 0) wsum[tid >> 5] = sq;
    __syncthreads();
    float nrm = sqrtf(wsum[l*4] + wsum[l*4+1] + wsum[l*4+2] + wsum[l*4+3]);
    float q = v / fmaxf(nrm, 1e-12f);
    qs[l][c] = q;
    __syncthreads();
    if (tid < 16) {
        int n = tid >> 2, m = tid & 3;
        float d = 0.f;
        for (int i = 0; i < CD; i++) d += qs[n][i] * qs[m][i];
        attnm[tid] = d / sqrtf((float)CD);
    }
    __syncthreads();
    if (tid < 4) {
        float mx = attnm[tid*4];
        for (int m = 1; m < 4; m++) mx = fmaxf(mx, attnm[tid*4+m]);
        float e[4], s = 0.f;
        for (int m = 0; m < 4; m++) { e[m] = expf(attnm[tid*4+m] - mx); s += e[m]; }
        for (int m = 0; m < 4; m++) prob[tid*4+m] = e[m] / s;
    }
    __syncthreads();
    float msg = prob[l*4+0]*qs[0][c] + prob[l*4+1]*qs[1][c]
              + prob[l*4+2]*qs[2][c] + prob[l*4+3]*qs[3][c];
    g_desc2[(l*CD + c)*KP + k] = 2.f*q + msg;
}

// =================================================================
// 6) fused proj (3-tap conv1d + relu) then projS (1x1). grid(8, L), 256 thr
// =================================================================
__global__ void __launch_bounds__(256)
projfused_kernel(const float* __restrict__ w1, const float* __restrict__ b1,
                 const float* __restrict__ w2, const float* __restrict__ b2) {
    const int l = blockIdx.y, kt = blockIdx.x;
    const int tx = threadIdx.x & 31, ty = threadIdx.x >> 5;
    const int k0 = kt * 32;
    __shared__ float Dt[128][34];
    __shared__ float wsbuf[16*384];
    for (int i = threadIdx.x; i < 128*34; i += 256) {
        int ci = i / 34, col = i - ci*34;
        int kk = k0 + col - 1;
        Dt[ci][col] = (kk >= 0 && kk < KP) ? g_desc2[(l*CD + ci)*KP + kk] : 0.f;
    }
    float acc[16];
    #pragma unroll
    for (int r = 0; r < 16; r++) acc[r] = 0.f;
    for (int ic = 0; ic < 128; ic += 16) {
        __syncthreads();
        for (int i = threadIdx.x; i < 16*384; i += 256) {
            int il = i / 384, rest = i - il*384;
            int o = rest / 3, d = rest - o*3;
            wsbuf[il*384 + rest] = w1[o*384 + (ic + il)*3 + d];
        }
        __syncthreads();
        #pragma unroll 4
        for (int il = 0; il < 16; il++) {
            float pm = Dt[ic+il][tx], p0 = Dt[ic+il][tx+1], pp = Dt[ic+il][tx+2];
            #pragma unroll
            for (int r = 0; r < 16; r++) {
                int o = ty*16 + r;
                acc[r] += wsbuf[il*384 + o*3]*pm + wsbuf[il*384 + o*3+1]*p0
                        + wsbuf[il*384 + o*3+2]*pp;
            }
        }
    }
    __syncthreads();   // everyone done reading Dt/wsbuf
    #pragma unroll
    for (int r = 0; r < 16; r++) {
        int o = ty*16 + r;
        float pv = fmaxf(acc[r] + b1[o], 0.f);
        g_proj[(l*CD + o)*KP + k0 + tx] = pv;
        Dt[o][tx] = pv;           // reuse Dt as proj tile [128 out][32 k]
        acc[r] = 0.f;
    }
    // ---- stage B: projS 1x1 ----
    for (int ic = 0; ic < 128; ic += 32) {
        __syncthreads();
        for (int i = threadIdx.x; i < 4096; i += 256) {
            int il = i & 31, o = i >> 5;
            wsbuf[il*128 + o] = w2[o*128 + ic + il];
        }
        __syncthreads();
        #pragma unroll 8
        for (int il = 0; il < 32; il++) {
            float p = Dt[ic+il][tx];
            #pragma unroll
            for (int r = 0; r < 16; r++)
                acc[r] += wsbuf[il*128 + ty*16 + r] * p;
        }
    }
    #pragma unroll
    for (int r = 0; r < 16; r++) {
        int o = ty*16 + r;
        g_s[(l*CD + o)*KP + k0 + tx] = acc[r] + b2[o];
    }
}

// =================================================================
// 7) per-(l,cd) row: stable argsort(-s), gather proj. grid(512), 256 thr
// =================================================================
__device__ __forceinline__ unsigned fkey(float f) {
    unsigned u = __float_as_uint(f);
    return (u & 0x80000000u) ? ~u : (u | 0x80000000u);
}
__global__ void __launch_bounds__(256) sortrow_kernel() {
    const int row = blockIdx.x;
    const int j = threadIdx.x;
    __shared__ unsigned long long sk[KP];
    float sv = g_s[row*KP + j];
    unsigned fk = fkey(sv) ^ 0xFFFFFFFFu;  // descending s
    sk[j] = (((unsigned long long)fk) << 32) | (unsigned)j;
    __syncthreads();
    for (int k2 = 2; k2 <= KP; k2 <<= 1)
        for (int jj = k2 >> 1; jj > 0; jj >>= 1) {
            int ixj = j ^ jj;
            if (ixj > j) {
                bool up = ((j & k2) == 0);
                unsigned long long a = sk[j], bb = sk[ixj];
                if ((a > bb) == up) { sk[j] = bb; sk[ixj] = a; }
            }
            __syncthreads();
        }
    int src = (int)(sk[j] & 0xFFFFFFFFull);
    g_sortd[row*KP + j] = g_proj[row*KP + src];
}

// 8) final: 1x1 conv 128->3. grid(12), 256 threads
__global__ void __launch_bounds__(256)
final_kernel(const float* __restrict__ w, const float* __restrict__ b) {
    const int lo = blockIdx.x;
    const int l = lo / 3, o = lo - l*3;
    const int j = threadIdx.x;
    float acc = b[o];
    for (int cd = 0; cd < CD; cd++)
        acc += w[o*CD + cd] * g_sortd[(l*CD + cd)*KP + j];
    g_final[lo*KP + j] = acc;
}

// 9) theta: subtract layer0, argmin|.| (first occurrence), build affine. 1 block
__global__ void __launch_bounds__(384) theta_kernel() {
    const int tid = threadIdx.x;
    const int wrp = tid >> 5, lane = tid & 31;
    __shared__ float md[L][3];
    if (wrp < 12) {
        int l = wrp / 3, o = wrp - l*3;
        unsigned long long best = 0xFFFFFFFFFFFFFFFFull;
        for (int j = lane; j < KP; j += 32) {
            float d = g_final[(l*3 + o)*KP + j] - g_final[o*KP + j];
            float a = fabsf(d);
            unsigned long long key = (((unsigned long long)__float_as_uint(a)) << 32) | (unsigned)j;
            best = (key < best) ? key : best;
        }
        #pragma unroll
        for (int s = 16; s > 0; s >>= 1) {
            unsigned long long oth = __shfl_xor_sync(0xffffffffu, best, s);
            best = (oth < best) ? oth : best;
        }
        if (lane == 0) md[l][o] = __uint_as_float((unsigned)(best >> 32));
    }
    __syncthreads();
    if (tid < L) {
        float th = md[tid][2], tx = md[tid][0], ty = md[tid][1];
        float cc = cosf(th), ss = sinf(th);
        g_theta[tid*6 + 0] = cc;  g_theta[tid*6 + 1] = -ss; g_theta[tid*6 + 2] = tx;
        g_theta[tid*6 + 3] = ss;  g_theta[tid*6 + 4] = cc;  g_theta[tid*6 + 5] = ty;
    }
}

// =================================================================
// 10) affine grid + bilinear sample, channel-parallel.
//     grid (H, C/8, L), 256 threads (j), 8 channels per thread.
// =================================================================
__global__ void __launch_bounds__(256)
sample_kernel(const float* __restrict__ feats, float* __restrict__ out) {
    const int i = blockIdx.x, c0 = blockIdx.y * 8, l = blockIdx.z;
    const int j = threadIdx.x;
    float t0 = g_theta[l*6+0], t1 = g_theta[l*6+1], t2 = g_theta[l*6+2];
    float t3 = g_theta[l*6+3], t4 = g_theta[l*6+4], t5 = g_theta[l*6+5];
    float X = (j + 0.5f) * (2.0f / W) - 1.0f;
    float Y = (i + 0.5f) * (2.0f / H) - 1.0f;
    float gx = t0*X + t1*Y + t2;
    float gy = t3*X + t4*Y + t5;
    float ix = ((gx + 1.0f) * W - 1.0f) * 0.5f;
    float iy = ((gy + 1.0f) * H - 1.0f) * 0.5f;
    float x0f = floorf(ix), y0f = floorf(iy);
    float x1f = x0f + 1.0f, y1f = y0f + 1.0f;
    float wa = (x1f - ix) * (y1f - iy);
    float wb = (ix - x0f) * (y1f - iy);
    float wc = (x1f - ix) * (iy - y0f);
    float wd = (ix - x0f) * (iy - y0f);
    bool vx0 = (x0f >= 0.f) && (x0f <= (float)(W-1));
    bool vx1 = (x1f >= 0.f) && (x1f <= (float)(W-1));
    bool vy0 = (y0f >= 0.f) && (y0f <= (float)(H-1));
    bool vy1 = (y1f >= 0.f) && (y1f <= (float)(H-1));
    int x0 = (int)fminf(fmaxf(x0f, 0.f), (float)(W-1));
    int x1 = (int)fminf(fmaxf(x1f, 0.f), (float)(W-1));
    int y0 = (int)fminf(fmaxf(y0f, 0.f), (float)(H-1));
    int y1 = (int)fminf(fmaxf(y1f, 0.f), (float)(H-1));
    bool va = vx0 && vy0, vb = vx1 && vy0, vc = vx0 && vy1, vd = vx1 && vy1;
    const int o00 = y0*W + x0, o01 = y0*W + x1, o10 = y1*W + x0, o11 = y1*W + x1;
    #pragma unroll
    for (int cc = 0; cc < 8; cc++) {
        const float* base = feats + (size_t)((l*C + c0 + cc)*H) * W;
        float A  = va ? base[o00] : 0.f;
        float B  = vb ? base[o01] : 0.f;
        float Cv = vc ? base[o10] : 0.f;
        float D  = vd ? base[o11] : 0.f;
        out[(size_t)((l*C + c0 + cc)*H + i)*W + j] = A*wa + B*wb + Cv*wc + D*wd;
    }
}

// =================================================================
extern "C" void kernel_launch(void* const* d_in, const int* in_sizes, int n_in,
                              void* d_out, int out_size) {
    (void)in_sizes; (void)n_in; (void)out_size;
    const float* feats   = (const float*)d_in[0];
    const float* convS_w = (const float*)d_in[1];
    const float* convS_b = (const float*)d_in[2];
    const float* convD_w = (const float*)d_in[3];
    const float* convD_b = (const float*)d_in[4];
    const float* proj_w  = (const float*)d_in[5];
    const float* proj_b  = (const float*)d_in[6];
    const float* projS_w = (const float*)d_in[7];
    const float* projS_b = (const float*)d_in[8];
    const float* final_w = (const float*)d_in[9];
    const float* final_b = (const float*)d_in[10];
    float* out = (float*)d_out;

    convS_kernel<<<dim3(W/64, H/16, L), 256>>>(feats, convS_w, convS_b);

    dim3 ng(W/32, H/32, L);
    nms1_kernel<<<ng, 1024>>>();
    nms23_kernel<<<ng, 1024>>>(0);   // g_mask  -> g_mask2
    nms23_kernel<<<ng, 1024>>>(1);   // g_mask2 -> g_mask

    topk_kernel<<<L, 1024>>>();

    descgemm_kernel<<<dim3(KP/32, KSPLIT, L), 256>>>(feats, convD_w);
    descnorm_attn_kernel<<<KP, 512>>>(convD_b);
    projfused_kernel<<<dim3(KP/32, L), 256>>>(proj_w, proj_b, projS_w, projS_b);
    sortrow_kernel<<<L*CD, KP>>>();
    final_kernel<<<L*3, KP>>>(final_w, final_b);
    theta_kernel<<<1, 384>>>();
    sample_kernel<<<dim3(H, C/8, L), 256>>>(feats, out);
}